// round 1
// baseline (speedup 1.0000x reference)
#include <cuda_runtime.h>
#include <math.h>

#define TT 512
#define BB 256
#define DIN 256
#define DLT 256

// output layout (floats): H[(T+1),B,DL], C[(T+1),B,DL], F[T,B,DL], I[T,B,DL], O[T,B,DL]
#define H_OFF 0
#define C_OFF ((TT + 1) * BB * DLT)          // 33,619,968
#define F_OFF (2 * (TT + 1) * BB * DLT)      // 67,239,936
#define I_OFF (F_OFF + TT * BB * DLT)        // 100,794,368
#define O_OFF (I_OFF + TT * BB * DLT)        // 134,348,800

__device__ __forceinline__ float sigm(float x) { return 1.0f / (1.0f + expf(-x)); }

// ---------------------------------------------------------------------------
// init: zero h0, c0 planes
// ---------------------------------------------------------------------------
__global__ void init_kernel(float* __restrict__ out)
{
    int idx = blockIdx.x * 256 + threadIdx.x;
    if (idx < BB * DLT) {
        out[H_OFF + idx] = 0.0f;
        out[C_OFF + idx] = 0.0f;
    }
}

// ---------------------------------------------------------------------------
// phase 1: Zx[t,b, gate, j] = X[t,b,:] @ Wg[j, 256:512] + bg[j]
// written into the final output slots (pre-activation):
//   g=0 (f) -> F[t,b,j]; g=1 (i) -> I[t,b,j]; g=2 (c~) -> C[t+1,b,j]; g=3 (o) -> O[t,b,j]
// GEMM: M = T*B = 131072, N = 1024 (4 gates x 256), K = 256
// tile 128(M) x 64(N), K-chunk 16, 256 threads, 8x4 micro
// ---------------------------------------------------------------------------
__global__ void __launch_bounds__(256) phase1_kernel(
    const float* __restrict__ X,
    const float* __restrict__ W0, const float* __restrict__ b0v,
    const float* __restrict__ W1, const float* __restrict__ b1v,
    const float* __restrict__ W2, const float* __restrict__ b2v,
    const float* __restrict__ W3, const float* __restrict__ b3v,
    float* __restrict__ out)
{
    __shared__ float As[128 * 16];   // [row][k], stride 16
    __shared__ float Bs[16 * 64];    // [k][col]

    const int bx = blockIdx.x;             // 0..15 : n-tile (gate*4 + colblock)
    const int m0 = blockIdx.y * 128;       // row tile
    const int g  = bx >> 2;
    const int j0 = (bx & 3) * 64;

    const float* Wg   = (g == 0) ? W0 : (g == 1) ? W1 : (g == 2) ? W2 : W3;
    const float* bias = (g == 0) ? b0v : (g == 1) ? b1v : (g == 2) ? b2v : b3v;

    const int tid = threadIdx.x;
    const int tn  = tid & 15;   // col group (4 cols)
    const int tm  = tid >> 4;   // row group (8 rows)

    float acc[8][4];
#pragma unroll
    for (int i = 0; i < 8; i++)
#pragma unroll
        for (int u = 0; u < 4; u++) acc[i][u] = 0.0f;

    for (int k0 = 0; k0 < 256; k0 += 16) {
        // load A tile: 128 rows x 16 k = 512 float4, 2 per thread
#pragma unroll
        for (int it = 0; it < 2; it++) {
            int idx = tid + it * 256;
            int row = idx >> 2;
            int q   = idx & 3;
            float4 v = *(const float4*)&X[(size_t)(m0 + row) * 256 + k0 + q * 4];
            *(float4*)&As[row * 16 + q * 4] = v;
        }
        // load B tile: 64 rows(j) x 16 k = 256 float4, 1 per thread, store transposed
        {
            int jr = tid >> 2;
            int q  = tid & 3;
            float4 v = *(const float4*)&Wg[(size_t)(j0 + jr) * 512 + 256 + k0 + q * 4];
            Bs[(q * 4 + 0) * 64 + jr] = v.x;
            Bs[(q * 4 + 1) * 64 + jr] = v.y;
            Bs[(q * 4 + 2) * 64 + jr] = v.z;
            Bs[(q * 4 + 3) * 64 + jr] = v.w;
        }
        __syncthreads();
#pragma unroll
        for (int kk = 0; kk < 16; kk++) {
            float4 b4 = *(const float4*)&Bs[kk * 64 + tn * 4];
#pragma unroll
            for (int i = 0; i < 8; i++) {
                float a = As[(tm * 8 + i) * 16 + kk];
                acc[i][0] += a * b4.x;
                acc[i][1] += a * b4.y;
                acc[i][2] += a * b4.z;
                acc[i][3] += a * b4.w;
            }
        }
        __syncthreads();
    }

    // epilogue: add bias, store pre-activations to final slots
    const int j = j0 + tn * 4;
    float4 bi4 = *(const float4*)&bias[j];
#pragma unroll
    for (int i = 0; i < 8; i++) {
        int m = m0 + tm * 8 + i;   // m = t*B + b
        float4 v;
        v.x = acc[i][0] + bi4.x;
        v.y = acc[i][1] + bi4.y;
        v.z = acc[i][2] + bi4.z;
        v.w = acc[i][3] + bi4.w;
        int idx;
        if (g == 0)      idx = F_OFF + m * DLT + j;
        else if (g == 1) idx = I_OFF + m * DLT + j;
        else if (g == 2) idx = C_OFF + (m + BB) * DLT + j;   // C[t+1] slot
        else             idx = O_OFF + m * DLT + j;
        *(float4*)&out[idx] = v;
    }
}

// ---------------------------------------------------------------------------
// step t: gates = h @ Wh^T (+ stashed Zx), activations, c/h update.
// grid (8,8): blockIdx.x -> j0 (32 cols), blockIdx.y -> b0 (32 rows)
// 256 threads: 4 gates x 64 threads, 4x4 micro over a 32x32 tile per gate
// smem 48 KB static: hs[256][32] transposed h tile + ws[4][32][32] weight chunk
// ---------------------------------------------------------------------------
__global__ void __launch_bounds__(256) step_kernel(
    const float* __restrict__ W0, const float* __restrict__ W1,
    const float* __restrict__ W2, const float* __restrict__ W3,
    float* __restrict__ out, int t)
{
    __shared__ float hs[256 * 32];   // [k][row], 32 KB
    __shared__ float ws[4 * 32 * 32]; // [g][k][col], 16 KB  (reused as exchange buffer)

    const int j0 = blockIdx.x * 32;
    const int b0 = blockIdx.y * 32;
    const int tid  = threadIdx.x;
    const int lane = tid & 31;
    const int w    = tid >> 5;

    // load full h tile (32 rows x 256 k), transposed, conflict-free
    const float* hsrc = out + H_OFF + t * (BB * DLT);
#pragma unroll
    for (int i = 0; i < 8; i++) {
        int q = w * 8 + i;   // 0..63
        float4 v = *(const float4*)&hsrc[(b0 + lane) * 256 + q * 4];
        hs[(q * 4 + 0) * 32 + lane] = v.x;
        hs[(q * 4 + 1) * 32 + lane] = v.y;
        hs[(q * 4 + 2) * 32 + lane] = v.z;
        hs[(q * 4 + 3) * 32 + lane] = v.w;
    }

    const int g  = tid >> 6;           // gate
    const int tr = (tid >> 3) & 7;     // row group
    const int tc = tid & 7;            // col group
    const int r0 = tr * 4, c0 = tc * 4;

    float acc[4][4];
#pragma unroll
    for (int i = 0; i < 4; i++)
#pragma unroll
        for (int u = 0; u < 4; u++) acc[i][u] = 0.0f;

    for (int kc = 0; kc < 256; kc += 32) {
        __syncthreads();   // also covers hs stores on first iteration
        // load weight chunk: 4 gates x 32 cols x 32 k = 1024 float4, 4/thread
#pragma unroll
        for (int i = 0; i < 4; i++) {
            int combo = w * 4 + i;       // 0..31
            int gg = combo >> 3;
            int q  = combo & 7;
            const float* Wgg = (gg == 0) ? W0 : (gg == 1) ? W1 : (gg == 2) ? W2 : W3;
            float4 v = *(const float4*)&Wgg[(size_t)(j0 + lane) * 512 + kc + q * 4];
            int base = gg * 1024 + (q * 4) * 32 + lane;
            ws[base + 0 ] = v.x;
            ws[base + 32] = v.y;
            ws[base + 64] = v.z;
            ws[base + 96] = v.w;
        }
        __syncthreads();
#pragma unroll 8
        for (int k = 0; k < 32; k++) {
            float4 a4 = *(const float4*)&hs[(kc + k) * 32 + r0];
            float4 w4 = *(const float4*)&ws[g * 1024 + k * 32 + c0];
            acc[0][0] += a4.x * w4.x; acc[0][1] += a4.x * w4.y; acc[0][2] += a4.x * w4.z; acc[0][3] += a4.x * w4.w;
            acc[1][0] += a4.y * w4.x; acc[1][1] += a4.y * w4.y; acc[1][2] += a4.y * w4.z; acc[1][3] += a4.y * w4.w;
            acc[2][0] += a4.z * w4.x; acc[2][1] += a4.z * w4.y; acc[2][2] += a4.z * w4.z; acc[2][3] += a4.z * w4.w;
            acc[3][0] += a4.w * w4.x; acc[3][1] += a4.w * w4.y; acc[3][2] += a4.w * w4.z; acc[3][3] += a4.w * w4.w;
        }
    }
    __syncthreads();   // done reading ws; it becomes the exchange buffer

    // add stashed Zx, activate, write to exchange buffer
    float* sg = ws;    // [4][32][32]
#pragma unroll
    for (int i = 0; i < 4; i++) {
        int b = b0 + r0 + i;
        int m = t * 256 + b;
        int idx;
        if (g == 0)      idx = F_OFF + m * DLT + j0 + c0;
        else if (g == 1) idx = I_OFF + m * DLT + j0 + c0;
        else if (g == 2) idx = C_OFF + (m + BB) * DLT + j0 + c0;
        else             idx = O_OFF + m * DLT + j0 + c0;
        float4 zx = *(const float4*)&out[idx];
        float4 r;
        r.x = acc[i][0] + zx.x;
        r.y = acc[i][1] + zx.y;
        r.z = acc[i][2] + zx.z;
        r.w = acc[i][3] + zx.w;
        if (g == 2) {
            r.x = tanhf(r.x); r.y = tanhf(r.y); r.z = tanhf(r.z); r.w = tanhf(r.w);
        } else {
            r.x = sigm(r.x); r.y = sigm(r.y); r.z = sigm(r.z); r.w = sigm(r.w);
        }
        *(float4*)&sg[g * 1024 + (r0 + i) * 32 + c0] = r;
    }
    __syncthreads();

    // elementwise LSTM update: 4 cells per thread
    {
        int re = tid >> 3;            // 0..31
        int ce = (tid & 7) * 4;       // 0..28
        float4 fv = *(const float4*)&sg[0 * 1024 + re * 32 + ce];
        float4 iv = *(const float4*)&sg[1 * 1024 + re * 32 + ce];
        float4 cv = *(const float4*)&sg[2 * 1024 + re * 32 + ce];
        float4 ov = *(const float4*)&sg[3 * 1024 + re * 32 + ce];
        int b   = b0 + re;
        int col = j0 + ce;
        float4 cold = *(const float4*)&out[C_OFF + t * (BB * DLT) + b * 256 + col];
        float4 cnew, hnew;
        cnew.x = fv.x * cold.x + iv.x * cv.x;
        cnew.y = fv.y * cold.y + iv.y * cv.y;
        cnew.z = fv.z * cold.z + iv.z * cv.z;
        cnew.w = fv.w * cold.w + iv.w * cv.w;
        hnew.x = ov.x * tanhf(cnew.x);
        hnew.y = ov.y * tanhf(cnew.y);
        hnew.z = ov.z * tanhf(cnew.z);
        hnew.w = ov.w * tanhf(cnew.w);
        int m = t * 256 + b;
        *(float4*)&out[F_OFF + m * DLT + col] = fv;
        *(float4*)&out[I_OFF + m * DLT + col] = iv;
        *(float4*)&out[O_OFF + m * DLT + col] = ov;
        *(float4*)&out[C_OFF + (t + 1) * (BB * DLT) + b * 256 + col] = cnew;
        *(float4*)&out[H_OFF + (t + 1) * (BB * DLT) + b * 256 + col] = hnew;
    }
}

// ---------------------------------------------------------------------------
extern "C" void kernel_launch(void* const* d_in, const int* in_sizes, int n_in,
                              void* d_out, int out_size)
{
    const float* X  = (const float*)d_in[0];
    const float* Wf = (const float*)d_in[1];
    const float* bf = (const float*)d_in[2];
    const float* Wi = (const float*)d_in[3];
    const float* bi = (const float*)d_in[4];
    const float* Wc = (const float*)d_in[5];
    const float* bc = (const float*)d_in[6];
    const float* Wo = (const float*)d_in[7];
    const float* bo = (const float*)d_in[8];
    float* out = (float*)d_out;

    init_kernel<<<256, 256>>>(out);
    phase1_kernel<<<dim3(16, 1024), 256>>>(X, Wf, bf, Wi, bi, Wc, bc, Wo, bo, out);
    for (int t = 0; t < TT; t++) {
        step_kernel<<<dim3(8, 8), 256>>>(Wf, Wi, Wc, Wo, out, t);
    }
}

// round 3
// speedup vs baseline: 1.8621x; 1.8621x over previous
#include <cuda_runtime.h>
#include <math.h>

#define TT 512
#define BB 256
#define DIN 256
#define DLT 256
#define NCTA 128

// output layout (floats): H[(T+1),B,DL], C[(T+1),B,DL], F[T,B,DL], I[T,B,DL], O[T,B,DL]
#define H_OFF 0
#define C_OFF ((TT + 1) * BB * DLT)
#define F_OFF (2 * (TT + 1) * BB * DLT)
#define I_OFF (F_OFF + TT * BB * DLT)
#define O_OFF (I_OFF + TT * BB * DLT)

// dynamic smem partition (float offsets)
#define WS_OFF 0                    // 128 cols x 256 k          = 32768 floats
#define HS_OFF 32768                // 16 rows x 260 (padded)    = 4160
#define SG_OFF (32768 + 4160)       // 4 gates x 16 b x 34 pitch = 2176
#define CS_OFF (32768 + 4160 + 2176)// 512 c-state floats
#define SMEM_FLOATS (32768 + 4160 + 2176 + 512)
#define SMEM_BYTES (SMEM_FLOATS * 4)

__device__ unsigned int g_count = 0;
__device__ unsigned int g_gen = 0;

__device__ __forceinline__ float sigm(float x) { return 1.0f / (1.0f + expf(-x)); }

__device__ __forceinline__ unsigned int ld_acquire_gpu(const unsigned int* p)
{
    unsigned int v;
    asm volatile("ld.acquire.gpu.global.u32 %0, [%1];" : "=r"(v) : "l"(p) : "memory");
    return v;
}

__device__ __forceinline__ void red_release_add(unsigned int* p, unsigned int v)
{
    asm volatile("red.release.gpu.global.add.u32 [%0], %1;" :: "l"(p), "r"(v) : "memory");
}

__device__ __forceinline__ void grid_barrier(unsigned target)
{
    __syncthreads();
    if (threadIdx.x == 0) {
        __threadfence();                        // publish this CTA's writes
        if (atomicAdd(&g_count, 1) == NCTA - 1) {
            atomicExch(&g_count, 0);            // reset BEFORE release
            red_release_add(&g_gen, 1);         // release: all prior writes visible
        } else {
            while (ld_acquire_gpu(&g_gen) != target) { __nanosleep(64); }
        }
        __threadfence();                        // order subsequent reads
    }
    __syncthreads();
}

// ---------------------------------------------------------------------------
// phase 1: x-side pre-activations for all gates/timesteps, stashed into the
// final output slots (f->F[t], i->I[t], c~->C[t+1], o->O[t]).
// ---------------------------------------------------------------------------
__global__ void __launch_bounds__(256) phase1_kernel(
    const float* __restrict__ X,
    const float* __restrict__ W0, const float* __restrict__ b0v,
    const float* __restrict__ W1, const float* __restrict__ b1v,
    const float* __restrict__ W2, const float* __restrict__ b2v,
    const float* __restrict__ W3, const float* __restrict__ b3v,
    float* __restrict__ out)
{
    __shared__ float As[128 * 16];
    __shared__ float Bs[16 * 64];

    const int bx = blockIdx.x;
    const int m0 = blockIdx.y * 128;
    const int g  = bx >> 2;
    const int j0 = (bx & 3) * 64;

    const float* Wg   = (g == 0) ? W0 : (g == 1) ? W1 : (g == 2) ? W2 : W3;
    const float* bias = (g == 0) ? b0v : (g == 1) ? b1v : (g == 2) ? b2v : b3v;

    const int tid = threadIdx.x;
    const int tn  = tid & 15;
    const int tm  = tid >> 4;

    float acc[8][4];
#pragma unroll
    for (int i = 0; i < 8; i++)
#pragma unroll
        for (int u = 0; u < 4; u++) acc[i][u] = 0.0f;

    for (int k0 = 0; k0 < 256; k0 += 16) {
#pragma unroll
        for (int it = 0; it < 2; it++) {
            int idx = tid + it * 256;
            int row = idx >> 2;
            int q   = idx & 3;
            float4 v = *(const float4*)&X[(size_t)(m0 + row) * 256 + k0 + q * 4];
            *(float4*)&As[row * 16 + q * 4] = v;
        }
        {
            int jr = tid >> 2;
            int q  = tid & 3;
            float4 v = *(const float4*)&Wg[(size_t)(j0 + jr) * 512 + 256 + k0 + q * 4];
            Bs[(q * 4 + 0) * 64 + jr] = v.x;
            Bs[(q * 4 + 1) * 64 + jr] = v.y;
            Bs[(q * 4 + 2) * 64 + jr] = v.z;
            Bs[(q * 4 + 3) * 64 + jr] = v.w;
        }
        __syncthreads();
#pragma unroll
        for (int kk = 0; kk < 16; kk++) {
            float4 b4 = *(const float4*)&Bs[kk * 64 + tn * 4];
#pragma unroll
            for (int i = 0; i < 8; i++) {
                float a = As[(tm * 8 + i) * 16 + kk];
                acc[i][0] += a * b4.x;
                acc[i][1] += a * b4.y;
                acc[i][2] += a * b4.z;
                acc[i][3] += a * b4.w;
            }
        }
        __syncthreads();
    }

    const int j = j0 + tn * 4;
    float4 bi4 = *(const float4*)&bias[j];
#pragma unroll
    for (int i = 0; i < 8; i++) {
        int m = m0 + tm * 8 + i;
        float4 v;
        v.x = acc[i][0] + bi4.x;
        v.y = acc[i][1] + bi4.y;
        v.z = acc[i][2] + bi4.z;
        v.w = acc[i][3] + bi4.w;
        int idx;
        if (g == 0)      idx = F_OFF + m * DLT + j;
        else if (g == 1) idx = I_OFF + m * DLT + j;
        else if (g == 2) idx = C_OFF + (m + BB) * DLT + j;
        else             idx = O_OFF + m * DLT + j;
        *(float4*)&out[idx] = v;
    }
}

// ---------------------------------------------------------------------------
// persistent recurrence kernel: 128 CTAs = 16 b-tiles(16 rows) x 8 j-tiles
// (32 j-cols x 4 gates = 128 CTA-columns). Weights cached in smem once.
// Per step: load h tile -> warp-broadcast GEMM -> activate -> c/h update ->
// grid barrier.
// ---------------------------------------------------------------------------
__global__ void __launch_bounds__(256) persist_kernel(
    const float* __restrict__ W0, const float* __restrict__ W1,
    const float* __restrict__ W2, const float* __restrict__ W3,
    float* __restrict__ out)
{
    extern __shared__ float smem[];
    float* ws = smem + WS_OFF;   // [jc 0..127][k 0..255]
    float* hs = smem + HS_OFF;   // [b 0..15][k], pitch 260
    float* sg = smem + SG_OFF;   // [g][b][jl], pitch 34
    float* cs = smem + CS_OFF;   // [b*32+jl] c state

    const int tid = threadIdx.x;
    const int bt = blockIdx.x >> 3;
    const int jt = blockIdx.x & 7;
    const int b0 = bt * 16;
    const int j0 = jt * 32;

    __shared__ unsigned s_gen0;
    if (tid == 0) s_gen0 = ld_acquire_gpu(&g_gen);

    // ---- load weight slice once: 4 gates x 32 j x 256 k ----
#pragma unroll
    for (int it = 0; it < 32; it++) {
        int idx = tid + it * 256;      // float4 index 0..8191
        int jc = idx >> 6;
        int kq = idx & 63;
        int g  = jc >> 5;
        int jr = j0 + (jc & 31);
        const float* Wg = (g == 0) ? W0 : (g == 1) ? W1 : (g == 2) ? W2 : W3;
        float4 v = *(const float4*)&Wg[(size_t)jr * 512 + kq * 4];
        *(float4*)&ws[jc * 256 + kq * 4] = v;
    }

    // ---- init: zero c state, zero H0/C0 tiles in gmem ----
    {
        int cell = tid * 2;
        int b  = cell >> 5;
        int jl = cell & 31;
        float2 z = make_float2(0.0f, 0.0f);
        *(float2*)&cs[cell] = z;
        *(float2*)&out[H_OFF + (b0 + b) * DLT + j0 + jl] = z;
        *(float2*)&out[C_OFF + (b0 + b) * DLT + j0 + jl] = z;
    }

    __syncthreads();
    const unsigned base_gen = s_gen0;
    grid_barrier(base_gen + 1);    // init + weights visible everywhere

    // thread roles for GEMM
    const int w    = tid >> 5;
    const int lane = tid & 31;
    const int b    = lane & 15;        // row within b-tile
    const int jh   = lane >> 4;        // 0/1
    const int jc0  = w * 16 + jh * 8;  // 8 CTA-columns
    const int g    = jc0 >> 5;         // gate of this warp-half
    const int jl0  = jc0 & 31;         // column within gate

    for (int t = 0; t < TT; t++) {
        // ---- stage h tile: 16 rows x 256 k ----
        const float* hsrc = out + H_OFF + t * (BB * DLT);
#pragma unroll
        for (int it = 0; it < 4; it++) {
            int idx = tid + it * 256;      // 0..1023
            int br = idx >> 6;
            int kq = idx & 63;
            float4 v = *(const float4*)&hsrc[(b0 + br) * 256 + kq * 4];
            *(float4*)&hs[br * 260 + kq * 4] = v;
        }
        __syncthreads();

        // ---- GEMM: acc[j] = sum_k h[b,k] * ws[jc0+j, k] ----
        float acc[8];
#pragma unroll
        for (int j = 0; j < 8; j++) acc[j] = 0.0f;

#pragma unroll 4
        for (int k = 0; k < 256; k += 4) {
            float4 h4 = *(const float4*)&hs[b * 260 + k];
#pragma unroll
            for (int j = 0; j < 8; j++) {
                float4 w4 = *(const float4*)&ws[(jc0 + j) * 256 + k];
                acc[j] += h4.x * w4.x + h4.y * w4.y + h4.z * w4.z + h4.w * w4.w;
            }
        }

        // ---- epilogue: add stashed x-side pre-activation, activate ----
        {
            int mrow = t * BB + b0 + b;
            int stash;
            if (g == 0)      stash = F_OFF + mrow * DLT + j0 + jl0;
            else if (g == 1) stash = I_OFF + mrow * DLT + j0 + jl0;
            else if (g == 2) stash = C_OFF + (mrow + BB) * DLT + j0 + jl0;
            else             stash = O_OFF + mrow * DLT + j0 + jl0;
            float4 z0 = *(const float4*)&out[stash];
            float4 z1 = *(const float4*)&out[stash + 4];
            float v[8];
            v[0] = acc[0] + z0.x; v[1] = acc[1] + z0.y;
            v[2] = acc[2] + z0.z; v[3] = acc[3] + z0.w;
            v[4] = acc[4] + z1.x; v[5] = acc[5] + z1.y;
            v[6] = acc[6] + z1.z; v[7] = acc[7] + z1.w;
            float* sgp = &sg[(g * 16 + b) * 34 + jl0];
            if (g == 2) {
#pragma unroll
                for (int j = 0; j < 8; j++) sgp[j] = tanhf(v[j]);
            } else {
#pragma unroll
                for (int j = 0; j < 8; j++) sgp[j] = sigm(v[j]);
            }
        }
        __syncthreads();

        // ---- elementwise LSTM update: 2 cells per thread ----
        {
            int cell = tid * 2;
            int bb = cell >> 5;
            int jl = cell & 31;
            float2 fv = *(const float2*)&sg[(0 * 16 + bb) * 34 + jl];
            float2 iv = *(const float2*)&sg[(1 * 16 + bb) * 34 + jl];
            float2 cv = *(const float2*)&sg[(2 * 16 + bb) * 34 + jl];
            float2 ov = *(const float2*)&sg[(3 * 16 + bb) * 34 + jl];
            float2 cold = *(const float2*)&cs[cell];
            float2 cnew, hnew;
            cnew.x = fv.x * cold.x + iv.x * cv.x;
            cnew.y = fv.y * cold.y + iv.y * cv.y;
            hnew.x = ov.x * tanhf(cnew.x);
            hnew.y = ov.y * tanhf(cnew.y);
            *(float2*)&cs[cell] = cnew;
            int mrow = t * BB + b0 + bb;
            int jgl  = j0 + jl;
            *(float2*)&out[F_OFF + mrow * DLT + jgl] = fv;
            *(float2*)&out[I_OFF + mrow * DLT + jgl] = iv;
            *(float2*)&out[O_OFF + mrow * DLT + jgl] = ov;
            *(float2*)&out[C_OFF + (mrow + BB) * DLT + jgl] = cnew;
            *(float2*)&out[H_OFF + (mrow + BB) * DLT + jgl] = hnew;
        }

        grid_barrier(base_gen + 2 + t);
    }
}

// ---------------------------------------------------------------------------
extern "C" void kernel_launch(void* const* d_in, const int* in_sizes, int n_in,
                              void* d_out, int out_size)
{
    const float* X  = (const float*)d_in[0];
    const float* Wf = (const float*)d_in[1];
    const float* bf = (const float*)d_in[2];
    const float* Wi = (const float*)d_in[3];
    const float* bi = (const float*)d_in[4];
    const float* Wc = (const float*)d_in[5];
    const float* bc = (const float*)d_in[6];
    const float* Wo = (const float*)d_in[7];
    const float* bo = (const float*)d_in[8];
    float* out = (float*)d_out;

    cudaFuncSetAttribute(persist_kernel,
                         cudaFuncAttributeMaxDynamicSharedMemorySize, SMEM_BYTES);

    phase1_kernel<<<dim3(16, 1024), 256>>>(X, Wf, bf, Wi, bi, Wc, bc, Wo, bo, out);
    persist_kernel<<<NCTA, 256, SMEM_BYTES>>>(Wf, Wi, Wc, Wo, out);
}

// round 4
// speedup vs baseline: 2.8829x; 1.5482x over previous
#include <cuda_runtime.h>
#include <cuda_bf16.h>
#include <math.h>
#include <stdint.h>

#define TT 512
#define BB 256
#define DIN 256
#define DLT 256
#define NCTA 128

// output layout (floats): H[(T+1),B,DL], C[(T+1),B,DL], F[T,B,DL], I[T,B,DL], O[T,B,DL]
#define H_OFF 0
#define C_OFF ((TT + 1) * BB * DLT)
#define F_OFF (2 * (TT + 1) * BB * DLT)
#define I_OFF (F_OFF + TT * BB * DLT)
#define O_OFF (I_OFF + TT * BB * DLT)

__device__ unsigned int g_count = 0;
__device__ unsigned int g_gen = 0;

__device__ __forceinline__ float sigm(float x) { return 1.0f / (1.0f + expf(-x)); }

__device__ __forceinline__ unsigned int ld_acquire_gpu(const unsigned int* p)
{
    unsigned int v;
    asm volatile("ld.acquire.gpu.global.u32 %0, [%1];" : "=r"(v) : "l"(p) : "memory");
    return v;
}
__device__ __forceinline__ void red_release_add(unsigned int* p, unsigned int v)
{
    asm volatile("red.release.gpu.global.add.u32 [%0], %1;" :: "l"(p), "r"(v) : "memory");
}
__device__ __forceinline__ void grid_barrier(unsigned target)
{
    __syncthreads();
    if (threadIdx.x == 0) {
        __threadfence();
        if (atomicAdd(&g_count, 1) == NCTA - 1) {
            atomicExch(&g_count, 0);
            red_release_add(&g_gen, 1);
        } else {
            while (ld_acquire_gpu(&g_gen) != target) { __nanosleep(64); }
        }
        __threadfence();
    }
    __syncthreads();
}

// split a pair of floats into bf16 hi / lo packed u32
__device__ __forceinline__ void split2(float x, float y, uint32_t& hi, uint32_t& lo)
{
    __nv_bfloat16 hx = __float2bfloat16(x);
    __nv_bfloat16 hy = __float2bfloat16(y);
    __nv_bfloat16 lx = __float2bfloat16(x - __bfloat162float(hx));
    __nv_bfloat16 ly = __float2bfloat16(y - __bfloat162float(hy));
    __nv_bfloat162 h2 = __halves2bfloat162(hx, hy);
    __nv_bfloat162 l2 = __halves2bfloat162(lx, ly);
    hi = *(uint32_t*)&h2;
    lo = *(uint32_t*)&l2;
}

// D += A(16x16 bf16,row) x B(16x8 bf16,col)  fp32 accum
__device__ __forceinline__ void mma16816(float* d, const uint32_t* a, const uint32_t* b)
{
    asm volatile(
        "mma.sync.aligned.m16n8k16.row.col.f32.bf16.bf16.f32 "
        "{%0,%1,%2,%3}, {%4,%5,%6,%7}, {%8,%9}, {%0,%1,%2,%3};"
        : "+f"(d[0]), "+f"(d[1]), "+f"(d[2]), "+f"(d[3])
        : "r"(a[0]), "r"(a[1]), "r"(a[2]), "r"(a[3]), "r"(b[0]), "r"(b[1]));
}

__device__ __forceinline__ uint32_t ldbf2(const __nv_bfloat16* p) { return *(const uint32_t*)p; }

// ---------------------------------------------------------------------------
// phase 1 (tensor core): x-side pre-activations for all gates/timesteps,
// stashed into the final output slots (f->F[t], i->I[t], c~->C[t+1], o->O[t]).
// CTA tile 128m x 64n, K=256 in chunks of 32, split-bf16 3-pass mma.
// ---------------------------------------------------------------------------
#define P1S 40   // smem k-stride (bf16) for 32-k chunk, padded

__global__ void __launch_bounds__(256) phase1_kernel(
    const float* __restrict__ X,
    const float* __restrict__ W0, const float* __restrict__ b0v,
    const float* __restrict__ W1, const float* __restrict__ b1v,
    const float* __restrict__ W2, const float* __restrict__ b2v,
    const float* __restrict__ W3, const float* __restrict__ b3v,
    float* __restrict__ out)
{
    __shared__ __nv_bfloat16 AsH[128 * P1S];
    __shared__ __nv_bfloat16 AsL[128 * P1S];
    __shared__ __nv_bfloat16 BsH[64 * P1S];
    __shared__ __nv_bfloat16 BsL[64 * P1S];

    const int bx = blockIdx.x;
    const int m0 = blockIdx.y * 128;
    const int g  = bx >> 2;
    const int j0 = (bx & 3) * 64;

    const float* Wg   = (g == 0) ? W0 : (g == 1) ? W1 : (g == 2) ? W2 : W3;
    const float* bias = (g == 0) ? b0v : (g == 1) ? b1v : (g == 2) ? b2v : b3v;

    const int tid  = threadIdx.x;
    const int warp = tid >> 5;
    const int lane = tid & 31;
    const int wm = warp >> 1;     // 0..3 : 32-row slab
    const int wn = warp & 1;      // 0..1 : 32-col slab
    const int lg = lane >> 2;     // group 0..7
    const int tq = lane & 3;      // quad  0..3

    float acc[2][4][4];
#pragma unroll
    for (int i = 0; i < 2; i++)
#pragma unroll
        for (int j = 0; j < 4; j++)
#pragma unroll
            for (int u = 0; u < 4; u++) acc[i][j][u] = 0.0f;

    for (int c0 = 0; c0 < 256; c0 += 32) {
        // load + split X chunk: 128 rows x 32 k
#pragma unroll
        for (int it = 0; it < 4; it++) {
            int idx = tid + it * 256;    // 0..1023 float4
            int row = idx >> 3;
            int q   = idx & 7;
            float4 v = *(const float4*)&X[(size_t)(m0 + row) * 256 + c0 + q * 4];
            uint32_t h01, l01, h23, l23;
            split2(v.x, v.y, h01, l01);
            split2(v.z, v.w, h23, l23);
            int base = row * P1S + q * 4;
            *(uint32_t*)&AsH[base]     = h01;
            *(uint32_t*)&AsH[base + 2] = h23;
            *(uint32_t*)&AsL[base]     = l01;
            *(uint32_t*)&AsL[base + 2] = l23;
        }
        // load + split W chunk: 64 rows x 32 k (x-side cols 256..511)
#pragma unroll
        for (int it = 0; it < 2; it++) {
            int idx = tid + it * 256;    // 0..511 float4
            int row = idx >> 3;
            int q   = idx & 7;
            float4 v = *(const float4*)&Wg[(size_t)(j0 + row) * 512 + 256 + c0 + q * 4];
            uint32_t h01, l01, h23, l23;
            split2(v.x, v.y, h01, l01);
            split2(v.z, v.w, h23, l23);
            int base = row * P1S + q * 4;
            *(uint32_t*)&BsH[base]     = h01;
            *(uint32_t*)&BsH[base + 2] = h23;
            *(uint32_t*)&BsL[base]     = l01;
            *(uint32_t*)&BsL[base + 2] = l23;
        }
        __syncthreads();

#pragma unroll
        for (int kk = 0; kk < 32; kk += 16) {
            uint32_t ah[2][4], al[2][4], bh[4][2], bl[4][2];
#pragma unroll
            for (int i = 0; i < 2; i++) {
                int r = (wm * 32 + i * 16 + lg) * P1S + kk + tq * 2;
                ah[i][0] = ldbf2(&AsH[r]);
                ah[i][1] = ldbf2(&AsH[r + 8 * P1S]);
                ah[i][2] = ldbf2(&AsH[r + 8]);
                ah[i][3] = ldbf2(&AsH[r + 8 * P1S + 8]);
                al[i][0] = ldbf2(&AsL[r]);
                al[i][1] = ldbf2(&AsL[r + 8 * P1S]);
                al[i][2] = ldbf2(&AsL[r + 8]);
                al[i][3] = ldbf2(&AsL[r + 8 * P1S + 8]);
            }
#pragma unroll
            for (int j = 0; j < 4; j++) {
                int c = (wn * 32 + j * 8 + lg) * P1S + kk + tq * 2;
                bh[j][0] = ldbf2(&BsH[c]);
                bh[j][1] = ldbf2(&BsH[c + 8]);
                bl[j][0] = ldbf2(&BsL[c]);
                bl[j][1] = ldbf2(&BsL[c + 8]);
            }
#pragma unroll
            for (int i = 0; i < 2; i++)
#pragma unroll
                for (int j = 0; j < 4; j++) {
                    mma16816(acc[i][j], ah[i], bh[j]);
                    mma16816(acc[i][j], ah[i], bl[j]);
                    mma16816(acc[i][j], al[i], bh[j]);
                }
        }
        __syncthreads();
    }

    // epilogue: +bias, store pre-activations to final slots
#pragma unroll
    for (int i = 0; i < 2; i++) {
#pragma unroll
        for (int j = 0; j < 4; j++) {
            int col = j0 + wn * 32 + j * 8 + tq * 2;
            float bx = bias[col], by = bias[col + 1];
            int row0 = m0 + wm * 32 + i * 16 + lg;
#pragma unroll
            for (int h = 0; h < 2; h++) {
                int m = row0 + h * 8;
                float2 v;
                v.x = acc[i][j][h * 2 + 0] + bx;
                v.y = acc[i][j][h * 2 + 1] + by;
                int idx;
                if (g == 0)      idx = F_OFF + m * DLT + col;
                else if (g == 1) idx = I_OFF + m * DLT + col;
                else if (g == 2) idx = C_OFF + (m + BB) * DLT + col;
                else             idx = O_OFF + m * DLT + col;
                *(float2*)&out[idx] = v;
            }
        }
    }
}

// ---------------------------------------------------------------------------
// persistent recurrence kernel (tensor core): 128 CTAs = 16 b-tiles(16 rows)
// x 8 j-tiles (32 j x 4 gates = 128 CTA-cols). Weights split to bf16 hi/lo in
// smem once. Per step: convert h -> mma (3-pass split) -> activate -> update
// -> grid barrier.
// ---------------------------------------------------------------------------
#define PWS 264                              // k-stride (bf16), padded
#define WSH_B 0                              // ws_hi: 128*264*2 = 67584
#define WSL_B 67584
#define HSH_B (2 * 67584)                    // hs_hi: 16*264*2 = 8448
#define HSL_B (2 * 67584 + 8448)
#define SG_B  (2 * 67584 + 2 * 8448)         // float[4*16*34] = 8704
#define CS_B  (SG_B + 8704)                  // float[512] = 2048
#define PSMEM (CS_B + 2048)                  // 162816 bytes

__global__ void __launch_bounds__(256) persist_kernel(
    const float* __restrict__ W0, const float* __restrict__ W1,
    const float* __restrict__ W2, const float* __restrict__ W3,
    float* __restrict__ out)
{
    extern __shared__ char smem[];
    __nv_bfloat16* wsH = (__nv_bfloat16*)(smem + WSH_B);
    __nv_bfloat16* wsL = (__nv_bfloat16*)(smem + WSL_B);
    __nv_bfloat16* hsH = (__nv_bfloat16*)(smem + HSH_B);
    __nv_bfloat16* hsL = (__nv_bfloat16*)(smem + HSL_B);
    float* sg = (float*)(smem + SG_B);
    float* cs = (float*)(smem + CS_B);

    const int tid = threadIdx.x;
    const int bt = blockIdx.x >> 3;
    const int jt = blockIdx.x & 7;
    const int b0 = bt * 16;
    const int j0 = jt * 32;

    __shared__ unsigned s_gen0;
    if (tid == 0) s_gen0 = ld_acquire_gpu(&g_gen);

    // ---- load + split weight slice once: 4 gates x 32 j x 256 k ----
#pragma unroll
    for (int it = 0; it < 32; it++) {
        int idx = tid + it * 256;      // float4 index 0..8191
        int jc = idx >> 6;
        int kq = idx & 63;
        int gg = jc >> 5;
        int jr = j0 + (jc & 31);
        const float* Wg = (gg == 0) ? W0 : (gg == 1) ? W1 : (gg == 2) ? W2 : W3;
        float4 v = *(const float4*)&Wg[(size_t)jr * 512 + kq * 4];
        uint32_t h01, l01, h23, l23;
        split2(v.x, v.y, h01, l01);
        split2(v.z, v.w, h23, l23);
        int base = jc * PWS + kq * 4;
        *(uint32_t*)&wsH[base]     = h01;
        *(uint32_t*)&wsH[base + 2] = h23;
        *(uint32_t*)&wsL[base]     = l01;
        *(uint32_t*)&wsL[base + 2] = l23;
    }

    // ---- init: zero c state, zero H0/C0 tiles in gmem ----
    {
        int cell = tid * 2;
        int b  = cell >> 5;
        int jl = cell & 31;
        float2 z = make_float2(0.0f, 0.0f);
        *(float2*)&cs[cell] = z;
        *(float2*)&out[H_OFF + (b0 + b) * DLT + j0 + jl] = z;
        *(float2*)&out[C_OFF + (b0 + b) * DLT + j0 + jl] = z;
    }

    __syncthreads();
    const unsigned base_gen = s_gen0;
    grid_barrier(base_gen + 1);

    // warp roles
    const int warp = tid >> 5;          // 0..7 -> 16 CTA-cols each
    const int lane = tid & 31;
    const int lg = lane >> 2;           // 0..7
    const int tq = lane & 3;            // 0..3
    const int jc0  = warp * 16;
    const int gate = warp >> 1;
    const int jlb  = (warp & 1) * 16;

    for (int t = 0; t < TT; t++) {
        // ---- load + split h tile: 16 rows x 256 k ----
        const float* hsrc = out + H_OFF + t * (BB * DLT);
#pragma unroll
        for (int it = 0; it < 4; it++) {
            int idx = tid + it * 256;      // 0..1023 float4
            int br = idx >> 6;
            int kq = idx & 63;
            float4 v = *(const float4*)&hsrc[(b0 + br) * 256 + kq * 4];
            uint32_t h01, l01, h23, l23;
            split2(v.x, v.y, h01, l01);
            split2(v.z, v.w, h23, l23);
            int base = br * PWS + kq * 4;
            *(uint32_t*)&hsH[base]     = h01;
            *(uint32_t*)&hsH[base + 2] = h23;
            *(uint32_t*)&hsL[base]     = l01;
            *(uint32_t*)&hsL[base + 2] = l23;
        }
        __syncthreads();

        // ---- mma: out16x16 = h(16xK) x W(16 cols x K), 3-pass split ----
        float acc[2][4];
#pragma unroll
        for (int j = 0; j < 2; j++)
#pragma unroll
            for (int u = 0; u < 4; u++) acc[j][u] = 0.0f;

#pragma unroll
        for (int k16 = 0; k16 < 256; k16 += 16) {
            uint32_t ah[4], al[4], bh[2][2], bl[2][2];
            int r = lg * PWS + k16 + tq * 2;
            ah[0] = ldbf2(&hsH[r]);
            ah[1] = ldbf2(&hsH[r + 8 * PWS]);
            ah[2] = ldbf2(&hsH[r + 8]);
            ah[3] = ldbf2(&hsH[r + 8 * PWS + 8]);
            al[0] = ldbf2(&hsL[r]);
            al[1] = ldbf2(&hsL[r + 8 * PWS]);
            al[2] = ldbf2(&hsL[r + 8]);
            al[3] = ldbf2(&hsL[r + 8 * PWS + 8]);
#pragma unroll
            for (int j = 0; j < 2; j++) {
                int c = (jc0 + j * 8 + lg) * PWS + k16 + tq * 2;
                bh[j][0] = ldbf2(&wsH[c]);
                bh[j][1] = ldbf2(&wsH[c + 8]);
                bl[j][0] = ldbf2(&wsL[c]);
                bl[j][1] = ldbf2(&wsL[c + 8]);
            }
#pragma unroll
            for (int j = 0; j < 2; j++) {
                mma16816(acc[j], ah, bh[j]);
                mma16816(acc[j], ah, bl[j]);
                mma16816(acc[j], al, bh[j]);
            }
        }

        // ---- epilogue: add stashed x-side pre-activation, activate ----
#pragma unroll
        for (int j = 0; j < 2; j++) {
            int jl  = jlb + j * 8 + tq * 2;
            int col = j0 + jl;
#pragma unroll
            for (int h = 0; h < 2; h++) {
                int bl_ = lg + h * 8;                 // local b row
                int mrow = t * BB + b0 + bl_;
                int stash;
                if (gate == 0)      stash = F_OFF + mrow * DLT + col;
                else if (gate == 1) stash = I_OFF + mrow * DLT + col;
                else if (gate == 2) stash = C_OFF + (mrow + BB) * DLT + col;
                else                stash = O_OFF + mrow * DLT + col;
                float2 z = *(const float2*)&out[stash];
                float vx = acc[j][h * 2 + 0] + z.x;
                float vy = acc[j][h * 2 + 1] + z.y;
                float2 r;
                if (gate == 2) { r.x = tanhf(vx); r.y = tanhf(vy); }
                else           { r.x = sigm(vx);  r.y = sigm(vy);  }
                *(float2*)&sg[(gate * 16 + bl_) * 34 + jl] = r;
            }
        }
        __syncthreads();

        // ---- elementwise LSTM update: 2 cells per thread ----
        {
            int cell = tid * 2;
            int bb = cell >> 5;
            int jl = cell & 31;
            float2 fv = *(const float2*)&sg[(0 * 16 + bb) * 34 + jl];
            float2 iv = *(const float2*)&sg[(1 * 16 + bb) * 34 + jl];
            float2 cv = *(const float2*)&sg[(2 * 16 + bb) * 34 + jl];
            float2 ov = *(const float2*)&sg[(3 * 16 + bb) * 34 + jl];
            float2 cold = *(const float2*)&cs[cell];
            float2 cnew, hnew;
            cnew.x = fv.x * cold.x + iv.x * cv.x;
            cnew.y = fv.y * cold.y + iv.y * cv.y;
            hnew.x = ov.x * tanhf(cnew.x);
            hnew.y = ov.y * tanhf(cnew.y);
            *(float2*)&cs[cell] = cnew;
            int mrow = t * BB + b0 + bb;
            int jgl  = j0 + jl;
            *(float2*)&out[F_OFF + mrow * DLT + jgl] = fv;
            *(float2*)&out[I_OFF + mrow * DLT + jgl] = iv;
            *(float2*)&out[O_OFF + mrow * DLT + jgl] = ov;
            *(float2*)&out[C_OFF + (mrow + BB) * DLT + jgl] = cnew;
            *(float2*)&out[H_OFF + (mrow + BB) * DLT + jgl] = hnew;
        }

        grid_barrier(base_gen + 2 + t);
    }
}

// ---------------------------------------------------------------------------
extern "C" void kernel_launch(void* const* d_in, const int* in_sizes, int n_in,
                              void* d_out, int out_size)
{
    const float* X  = (const float*)d_in[0];
    const float* Wf = (const float*)d_in[1];
    const float* bf = (const float*)d_in[2];
    const float* Wi = (const float*)d_in[3];
    const float* bi = (const float*)d_in[4];
    const float* Wc = (const float*)d_in[5];
    const float* bc = (const float*)d_in[6];
    const float* Wo = (const float*)d_in[7];
    const float* bo = (const float*)d_in[8];
    float* out = (float*)d_out;

    cudaFuncSetAttribute(persist_kernel,
                         cudaFuncAttributeMaxDynamicSharedMemorySize, PSMEM);

    phase1_kernel<<<dim3(16, 1024), 256>>>(X, Wf, bf, Wi, bi, Wc, bc, Wo, bo, out);
    persist_kernel<<<NCTA, 256, PSMEM>>>(Wf, Wi, Wc, Wo, out);
}

// round 5
// speedup vs baseline: 3.2804x; 1.1379x over previous
#include <cuda_runtime.h>
#include <cuda_bf16.h>
#include <math.h>
#include <stdint.h>

#define TT 512
#define BB 256
#define DIN 256
#define DLT 256
#define NCTA 128
#define NGRP 8          // CTAs per barrier group (one b-tile)

// output layout (floats): H[(T+1),B,DL], C[(T+1),B,DL], F[T,B,DL], I[T,B,DL], O[T,B,DL]
#define H_OFF 0
#define C_OFF ((TT + 1) * BB * DLT)
#define F_OFF (2 * (TT + 1) * BB * DLT)
#define I_OFF (F_OFF + TT * BB * DLT)
#define O_OFF (I_OFF + TT * BB * DLT)

// bf16 hi/lo scratch for X and x-side weights
__device__ __nv_bfloat16 g_Xhi[TT * BB * DIN];
__device__ __nv_bfloat16 g_Xlo[TT * BB * DIN];
__device__ __nv_bfloat16 g_Wxhi[4 * DLT * DIN];
__device__ __nv_bfloat16 g_Wxlo[4 * DLT * DIN];

// per-group barrier state, 128B-separated
__device__ unsigned int g_cnt2[16 * 32];
__device__ unsigned int g_gen2[16 * 32];

__device__ __forceinline__ float sigm(float x) { return 1.0f / (1.0f + expf(-x)); }

__device__ __forceinline__ unsigned int ld_acquire_gpu(const unsigned int* p)
{
    unsigned int v;
    asm volatile("ld.acquire.gpu.global.u32 %0, [%1];" : "=r"(v) : "l"(p) : "memory");
    return v;
}
__device__ __forceinline__ void red_release_add(unsigned int* p, unsigned int v)
{
    asm volatile("red.release.gpu.global.add.u32 [%0], %1;" :: "l"(p), "r"(v) : "memory");
}
__device__ __forceinline__ void group_barrier(int slot, unsigned target)
{
    __syncthreads();
    if (threadIdx.x == 0) {
        __threadfence();
        if (atomicAdd(&g_cnt2[slot], 1) == NGRP - 1) {
            atomicExch(&g_cnt2[slot], 0);
            red_release_add(&g_gen2[slot], 1);
        } else {
            while (ld_acquire_gpu(&g_gen2[slot]) != target) { __nanosleep(32); }
        }
        __threadfence();
    }
    __syncthreads();
}

// split a pair of floats into bf16 hi / lo packed u32
__device__ __forceinline__ void split2(float x, float y, uint32_t& hi, uint32_t& lo)
{
    __nv_bfloat16 hx = __float2bfloat16(x);
    __nv_bfloat16 hy = __float2bfloat16(y);
    __nv_bfloat16 lx = __float2bfloat16(x - __bfloat162float(hx));
    __nv_bfloat16 ly = __float2bfloat16(y - __bfloat162float(hy));
    __nv_bfloat162 h2 = __halves2bfloat162(hx, hy);
    __nv_bfloat162 l2 = __halves2bfloat162(lx, ly);
    hi = *(uint32_t*)&h2;
    lo = *(uint32_t*)&l2;
}

// D += A(16x16 bf16,row) x B(16x8 bf16,col)  fp32 accum
__device__ __forceinline__ void mma16816(float* d, const uint32_t* a, const uint32_t* b)
{
    asm volatile(
        "mma.sync.aligned.m16n8k16.row.col.f32.bf16.bf16.f32 "
        "{%0,%1,%2,%3}, {%4,%5,%6,%7}, {%8,%9}, {%0,%1,%2,%3};"
        : "+f"(d[0]), "+f"(d[1]), "+f"(d[2]), "+f"(d[3])
        : "r"(a[0]), "r"(a[1]), "r"(a[2]), "r"(a[3]), "r"(b[0]), "r"(b[1]));
}

__device__ __forceinline__ uint32_t ldbf2(const __nv_bfloat16* p) { return *(const uint32_t*)p; }

// ---------------------------------------------------------------------------
// converters: fp32 -> bf16 hi/lo, done ONCE
// ---------------------------------------------------------------------------
__global__ void __launch_bounds__(256) convX_kernel(const float* __restrict__ X)
{
    int idx = blockIdx.x * 256 + threadIdx.x;      // float4 index
    if (idx < TT * BB * DIN / 4) {
        float4 v = *(const float4*)&X[(size_t)idx * 4];
        uint32_t h01, l01, h23, l23;
        split2(v.x, v.y, h01, l01);
        split2(v.z, v.w, h23, l23);
        ((uint2*)g_Xhi)[idx] = make_uint2(h01, h23);
        ((uint2*)g_Xlo)[idx] = make_uint2(l01, l23);
    }
}

__global__ void __launch_bounds__(256) convW_kernel(
    const float* __restrict__ W0, const float* __restrict__ W1,
    const float* __restrict__ W2, const float* __restrict__ W3)
{
    int idx = blockIdx.x * 256 + threadIdx.x;      // float4 index, 65536 total
    int g = idx >> 14;
    int j = (idx >> 6) & 255;
    int q = idx & 63;
    const float* Wg = (g == 0) ? W0 : (g == 1) ? W1 : (g == 2) ? W2 : W3;
    float4 v = *(const float4*)&Wg[(size_t)j * 512 + 256 + q * 4];
    uint32_t h01, l01, h23, l23;
    split2(v.x, v.y, h01, l01);
    split2(v.z, v.w, h23, l23);
    int d2 = g * 16384 + j * 64 + q;               // uint2 index
    ((uint2*)g_Wxhi)[d2] = make_uint2(h01, h23);
    ((uint2*)g_Wxlo)[d2] = make_uint2(l01, l23);
}

// ---------------------------------------------------------------------------
// phase 1 (tensor core, pre-converted inputs): CTA tile 128m x 128n.
// grid (8, 1024): bx -> gate = bx>>1, j0 = (bx&1)*128; by -> m-tile.
// K=256 in chunks of 32, split-bf16 3-pass mma. Stash results into final
// output slots (f->F[t], i->I[t], c~->C[t+1], o->O[t]).
// ---------------------------------------------------------------------------
#define P1S 40   // smem k-stride (bf16), padded

__global__ void __launch_bounds__(256) phase1_kernel(
    const float* __restrict__ b0v, const float* __restrict__ b1v,
    const float* __restrict__ b2v, const float* __restrict__ b3v,
    float* __restrict__ out)
{
    __shared__ __nv_bfloat16 AsH[128 * P1S];
    __shared__ __nv_bfloat16 AsL[128 * P1S];
    __shared__ __nv_bfloat16 BsH[128 * P1S];
    __shared__ __nv_bfloat16 BsL[128 * P1S];

    const int g  = blockIdx.x >> 1;
    const int j0 = (blockIdx.x & 1) * 128;
    const int m0 = blockIdx.y * 128;

    const float* bias = (g == 0) ? b0v : (g == 1) ? b1v : (g == 2) ? b2v : b3v;

    const int tid  = threadIdx.x;
    const int warp = tid >> 5;
    const int lane = tid & 31;
    const int wm = warp >> 1;     // 0..3 : 32-row slab
    const int wn = warp & 1;      // 0..1 : 64-col slab
    const int lg = lane >> 2;     // 0..7
    const int tq = lane & 3;      // 0..3

    float acc[2][8][4];
#pragma unroll
    for (int i = 0; i < 2; i++)
#pragma unroll
        for (int j = 0; j < 8; j++)
#pragma unroll
            for (int u = 0; u < 4; u++) acc[i][j][u] = 0.0f;

    for (int c0 = 0; c0 < 256; c0 += 32) {
        // A chunk: 128 rows x 32 k, hi+lo : 1024 uint4 -> 4/thread
#pragma unroll
        for (int it = 0; it < 2; it++) {
            int idx = tid + it * 256;     // 0..511
            int row = idx >> 2;
            int q   = idx & 3;
            int off = (m0 + row) * 256 + c0 + q * 8;
            int sb  = row * P1S + q * 8;
            *(uint4*)&AsH[sb] = *(const uint4*)&g_Xhi[off];
            *(uint4*)&AsL[sb] = *(const uint4*)&g_Xlo[off];
        }
        // B chunk: 128 n x 32 k, hi+lo
#pragma unroll
        for (int it = 0; it < 2; it++) {
            int idx = tid + it * 256;
            int row = idx >> 2;
            int q   = idx & 3;
            int off = g * 65536 + (j0 + row) * 256 + c0 + q * 8;
            int sb  = row * P1S + q * 8;
            *(uint4*)&BsH[sb] = *(const uint4*)&g_Wxhi[off];
            *(uint4*)&BsL[sb] = *(const uint4*)&g_Wxlo[off];
        }
        __syncthreads();

#pragma unroll
        for (int kk = 0; kk < 32; kk += 16) {
            uint32_t ah[2][4], al[2][4];
#pragma unroll
            for (int i = 0; i < 2; i++) {
                int r = (wm * 32 + i * 16 + lg) * P1S + kk + tq * 2;
                ah[i][0] = ldbf2(&AsH[r]);
                ah[i][1] = ldbf2(&AsH[r + 8 * P1S]);
                ah[i][2] = ldbf2(&AsH[r + 8]);
                ah[i][3] = ldbf2(&AsH[r + 8 * P1S + 8]);
                al[i][0] = ldbf2(&AsL[r]);
                al[i][1] = ldbf2(&AsL[r + 8 * P1S]);
                al[i][2] = ldbf2(&AsL[r + 8]);
                al[i][3] = ldbf2(&AsL[r + 8 * P1S + 8]);
            }
#pragma unroll
            for (int j = 0; j < 8; j++) {
                int c = (wn * 64 + j * 8 + lg) * P1S + kk + tq * 2;
                uint32_t bh[2], bl[2];
                bh[0] = ldbf2(&BsH[c]);
                bh[1] = ldbf2(&BsH[c + 8]);
                bl[0] = ldbf2(&BsL[c]);
                bl[1] = ldbf2(&BsL[c + 8]);
#pragma unroll
                for (int i = 0; i < 2; i++) {
                    mma16816(acc[i][j], ah[i], bh);
                    mma16816(acc[i][j], ah[i], bl);
                    mma16816(acc[i][j], al[i], bh);
                }
            }
        }
        __syncthreads();
    }

    // epilogue: +bias, store pre-activations to final slots
#pragma unroll
    for (int i = 0; i < 2; i++) {
#pragma unroll
        for (int j = 0; j < 8; j++) {
            int col = j0 + wn * 64 + j * 8 + tq * 2;
            float bx = bias[col], by = bias[col + 1];
            int row0 = m0 + wm * 32 + i * 16 + lg;
#pragma unroll
            for (int h = 0; h < 2; h++) {
                int m = row0 + h * 8;
                float2 v;
                v.x = acc[i][j][h * 2 + 0] + bx;
                v.y = acc[i][j][h * 2 + 1] + by;
                int idx;
                if (g == 0)      idx = F_OFF + m * DLT + col;
                else if (g == 1) idx = I_OFF + m * DLT + col;
                else if (g == 2) idx = C_OFF + (m + BB) * DLT + col;
                else             idx = O_OFF + m * DLT + col;
                *(float2*)&out[idx] = v;
            }
        }
    }
}

// ---------------------------------------------------------------------------
// persistent recurrence kernel: 128 CTAs = 16 b-tiles(16 rows) x 8 j-tiles.
// Barrier scope: only the 8 CTAs sharing a b-tile. Stash prefetched at loop
// top to hide gmem latency under h-convert + mma.
// ---------------------------------------------------------------------------
#define PWS 264                              // k-stride (bf16), padded
#define WSH_B 0                              // ws_hi: 128*264*2 = 67584
#define WSL_B 67584
#define HSH_B (2 * 67584)                    // hs_hi: 16*264*2 = 8448
#define HSL_B (2 * 67584 + 8448)
#define SG_B  (2 * 67584 + 2 * 8448)         // float[4*16*34] = 8704
#define CS_B  (SG_B + 8704)                  // float[512] = 2048
#define PSMEM (CS_B + 2048)

__global__ void __launch_bounds__(256) persist_kernel(
    const float* __restrict__ W0, const float* __restrict__ W1,
    const float* __restrict__ W2, const float* __restrict__ W3,
    float* __restrict__ out)
{
    extern __shared__ char smem[];
    __nv_bfloat16* wsH = (__nv_bfloat16*)(smem + WSH_B);
    __nv_bfloat16* wsL = (__nv_bfloat16*)(smem + WSL_B);
    __nv_bfloat16* hsH = (__nv_bfloat16*)(smem + HSH_B);
    __nv_bfloat16* hsL = (__nv_bfloat16*)(smem + HSL_B);
    float* sg = (float*)(smem + SG_B);
    float* cs = (float*)(smem + CS_B);

    const int tid = threadIdx.x;
    const int bt = blockIdx.x >> 3;
    const int jt = blockIdx.x & 7;
    const int b0 = bt * 16;
    const int j0 = jt * 32;
    const int slot = bt * 32;

    __shared__ unsigned s_gen0;
    if (tid == 0) s_gen0 = ld_acquire_gpu(&g_gen2[slot]);

    // ---- load + split weight slice once: 4 gates x 32 j x 256 k ----
#pragma unroll
    for (int it = 0; it < 32; it++) {
        int idx = tid + it * 256;
        int jc = idx >> 6;
        int kq = idx & 63;
        int gg = jc >> 5;
        int jr = j0 + (jc & 31);
        const float* Wg = (gg == 0) ? W0 : (gg == 1) ? W1 : (gg == 2) ? W2 : W3;
        float4 v = *(const float4*)&Wg[(size_t)jr * 512 + kq * 4];
        uint32_t h01, l01, h23, l23;
        split2(v.x, v.y, h01, l01);
        split2(v.z, v.w, h23, l23);
        int base = jc * PWS + kq * 4;
        *(uint32_t*)&wsH[base]     = h01;
        *(uint32_t*)&wsH[base + 2] = h23;
        *(uint32_t*)&wsL[base]     = l01;
        *(uint32_t*)&wsL[base + 2] = l23;
    }

    // ---- init: zero c state, zero H0/C0 tiles in gmem ----
    {
        int cell = tid * 2;
        int b  = cell >> 5;
        int jl = cell & 31;
        float2 z = make_float2(0.0f, 0.0f);
        *(float2*)&cs[cell] = z;
        *(float2*)&out[H_OFF + (b0 + b) * DLT + j0 + jl] = z;
        *(float2*)&out[C_OFF + (b0 + b) * DLT + j0 + jl] = z;
    }

    __syncthreads();
    const unsigned base_gen = s_gen0;
    group_barrier(slot, base_gen + 1);

    // warp roles
    const int warp = tid >> 5;
    const int lane = tid & 31;
    const int lg = lane >> 2;
    const int tq = lane & 3;
    const int jc0  = warp * 16;
    const int gate = warp >> 1;
    const int jlb  = (warp & 1) * 16;

    for (int t = 0; t < TT; t++) {
        // ---- prefetch x-side stash (independent of h) ----
        float2 zpre[2][2];
#pragma unroll
        for (int j = 0; j < 2; j++) {
            int col = j0 + jlb + j * 8 + tq * 2;
#pragma unroll
            for (int h = 0; h < 2; h++) {
                int mrow = t * BB + b0 + lg + h * 8;
                int stash;
                if (gate == 0)      stash = F_OFF + mrow * DLT + col;
                else if (gate == 1) stash = I_OFF + mrow * DLT + col;
                else if (gate == 2) stash = C_OFF + (mrow + BB) * DLT + col;
                else                stash = O_OFF + mrow * DLT + col;
                zpre[j][h] = *(const float2*)&out[stash];
            }
        }

        // ---- load + split h tile: 16 rows x 256 k ----
        const float* hsrc = out + H_OFF + t * (BB * DLT);
#pragma unroll
        for (int it = 0; it < 4; it++) {
            int idx = tid + it * 256;
            int br = idx >> 6;
            int kq = idx & 63;
            float4 v = *(const float4*)&hsrc[(b0 + br) * 256 + kq * 4];
            uint32_t h01, l01, h23, l23;
            split2(v.x, v.y, h01, l01);
            split2(v.z, v.w, h23, l23);
            int base = br * PWS + kq * 4;
            *(uint32_t*)&hsH[base]     = h01;
            *(uint32_t*)&hsH[base + 2] = h23;
            *(uint32_t*)&hsL[base]     = l01;
            *(uint32_t*)&hsL[base + 2] = l23;
        }
        __syncthreads();

        // ---- mma: 16x16 = h(16xK) x W(16 cols x K), 3-pass split ----
        float acc[2][4];
#pragma unroll
        for (int j = 0; j < 2; j++)
#pragma unroll
            for (int u = 0; u < 4; u++) acc[j][u] = 0.0f;

#pragma unroll
        for (int k16 = 0; k16 < 256; k16 += 16) {
            uint32_t ah[4], al[4], bh[2][2], bl[2][2];
            int r = lg * PWS + k16 + tq * 2;
            ah[0] = ldbf2(&hsH[r]);
            ah[1] = ldbf2(&hsH[r + 8 * PWS]);
            ah[2] = ldbf2(&hsH[r + 8]);
            ah[3] = ldbf2(&hsH[r + 8 * PWS + 8]);
            al[0] = ldbf2(&hsL[r]);
            al[1] = ldbf2(&hsL[r + 8 * PWS]);
            al[2] = ldbf2(&hsL[r + 8]);
            al[3] = ldbf2(&hsL[r + 8 * PWS + 8]);
#pragma unroll
            for (int j = 0; j < 2; j++) {
                int c = (jc0 + j * 8 + lg) * PWS + k16 + tq * 2;
                bh[j][0] = ldbf2(&wsH[c]);
                bh[j][1] = ldbf2(&wsH[c + 8]);
                bl[j][0] = ldbf2(&wsL[c]);
                bl[j][1] = ldbf2(&wsL[c + 8]);
            }
#pragma unroll
            for (int j = 0; j < 2; j++) {
                mma16816(acc[j], ah, bh[j]);
                mma16816(acc[j], ah, bl[j]);
                mma16816(acc[j], al, bh[j]);
            }
        }

        // ---- epilogue: add prefetched stash, activate ----
#pragma unroll
        for (int j = 0; j < 2; j++) {
            int jl = jlb + j * 8 + tq * 2;
#pragma unroll
            for (int h = 0; h < 2; h++) {
                int bl_ = lg + h * 8;
                float vx = acc[j][h * 2 + 0] + zpre[j][h].x;
                float vy = acc[j][h * 2 + 1] + zpre[j][h].y;
                float2 r;
                if (gate == 2) { r.x = tanhf(vx); r.y = tanhf(vy); }
                else           { r.x = sigm(vx);  r.y = sigm(vy);  }
                *(float2*)&sg[(gate * 16 + bl_) * 34 + jl] = r;
            }
        }
        __syncthreads();

        // ---- elementwise LSTM update: 2 cells per thread ----
        {
            int cell = tid * 2;
            int bb = cell >> 5;
            int jl = cell & 31;
            float2 fv = *(const float2*)&sg[(0 * 16 + bb) * 34 + jl];
            float2 iv = *(const float2*)&sg[(1 * 16 + bb) * 34 + jl];
            float2 cv = *(const float2*)&sg[(2 * 16 + bb) * 34 + jl];
            float2 ov = *(const float2*)&sg[(3 * 16 + bb) * 34 + jl];
            float2 cold = *(const float2*)&cs[cell];
            float2 cnew, hnew;
            cnew.x = fv.x * cold.x + iv.x * cv.x;
            cnew.y = fv.y * cold.y + iv.y * cv.y;
            hnew.x = ov.x * tanhf(cnew.x);
            hnew.y = ov.y * tanhf(cnew.y);
            *(float2*)&cs[cell] = cnew;
            int mrow = t * BB + b0 + bb;
            int jgl  = j0 + jl;
            *(float2*)&out[F_OFF + mrow * DLT + jgl] = fv;
            *(float2*)&out[I_OFF + mrow * DLT + jgl] = iv;
            *(float2*)&out[O_OFF + mrow * DLT + jgl] = ov;
            *(float2*)&out[C_OFF + (mrow + BB) * DLT + jgl] = cnew;
            *(float2*)&out[H_OFF + (mrow + BB) * DLT + jgl] = hnew;
        }

        group_barrier(slot, base_gen + 2 + t);
    }
}

// ---------------------------------------------------------------------------
extern "C" void kernel_launch(void* const* d_in, const int* in_sizes, int n_in,
                              void* d_out, int out_size)
{
    const float* X  = (const float*)d_in[0];
    const float* Wf = (const float*)d_in[1];
    const float* bf = (const float*)d_in[2];
    const float* Wi = (const float*)d_in[3];
    const float* bi = (const float*)d_in[4];
    const float* Wc = (const float*)d_in[5];
    const float* bc = (const float*)d_in[6];
    const float* Wo = (const float*)d_in[7];
    const float* bo = (const float*)d_in[8];
    float* out = (float*)d_out;

    cudaFuncSetAttribute(persist_kernel,
                         cudaFuncAttributeMaxDynamicSharedMemorySize, PSMEM);

    convX_kernel<<<TT * BB * DIN / 4 / 256, 256>>>(X);
    convW_kernel<<<256, 256>>>(Wf, Wi, Wc, Wo);
    phase1_kernel<<<dim3(8, 1024), 256>>>(bf, bi, bc, bo, out);
    persist_kernel<<<NCTA, 256, PSMEM>>>(Wf, Wi, Wc, Wo, out);
}